// round 17
// baseline (speedup 1.0000x reference)
#include <cuda_runtime.h>
#include <cuda_fp16.h>
#include <cstdint>
#include <cstddef>

// ---------------- problem constants ----------------
static constexpr int T_TOK = 8192;
static constexpr int HID   = 4096;
static constexpr int NOUT  = 6144;   // Q(4096) + K(1024) + V(1024)
static constexpr int QS    = 4096;
static constexpr int KVS   = 1024;
static constexpr int RANK  = 16;
static constexpr int SEXT  = 128;    // per-section ext: 8 slots * 16 ranks
static constexpr int KTOT2 = HID + SEXT;  // 4224 (GEMM2 K)
static constexpr int NT1   = 192;    // GEMM1 tile count (3 N x 64 M)
static constexpr int NW    = 104;    // conversion worker blocks; NW + NT1 = 296 = wave 1

// ---------------- scratch (static device memory; no allocation) ----------------
__device__ __align__(1024) __half g_xh[(size_t)T_TOK * HID];    // 67 MB (written by workers)
__device__ __align__(1024) __half g_wh[(size_t)NOUT * KTOT2];   // 51.9 MB (written by workers)
__device__ __align__(1024) __half g_ah[(size_t)3 * SEXT * HID]; //  3.1 MB (PERMUTED rows, prep1)
__device__ __align__(1024) __half g_xe[3][(size_t)T_TOK * SEXT];//  6.3 MB (written by G1 tiles)
__device__ __align__(128) unsigned g_done;        // G1-tile completion counter
__device__ __align__(128) unsigned g_wready;      // highest K-slab fully converted
__device__ __align__(128) unsigned g_slabcnt[66]; // per-slab worker-arrival counters

// ---------------- PTX helpers (base-target only: sm_70/80+ features) ----------------
__device__ __forceinline__ uint32_t smem_u32(const void* p) {
    uint32_t a;
    asm("{ .reg .u64 t; cvta.to.shared.u64 t, %1; cvt.u32.u64 %0, t; }" : "=r"(a) : "l"(p));
    return a;
}

__device__ __forceinline__ void cp_async16(uint32_t dst, const void* src) {
    asm volatile("cp.async.cg.shared.global [%0], [%1], 16;\n" :: "r"(dst), "l"(src) : "memory");
}

#define CP_COMMIT()  asm volatile("cp.async.commit_group;\n" ::: "memory")
#define CP_WAIT(n)   asm volatile("cp.async.wait_group %0;\n" :: "n"(n) : "memory")

__device__ __forceinline__ uint32_t sw128(uint32_t off) {
    return off ^ ((off >> 3) & 0x70);
}

__device__ __forceinline__ void ldmatrix_x4(uint32_t* r, uint32_t addr) {
    asm volatile("ldmatrix.sync.aligned.m8n8.x4.shared.b16 {%0,%1,%2,%3}, [%4];"
                 : "=r"(r[0]), "=r"(r[1]), "=r"(r[2]), "=r"(r[3]) : "r"(addr));
}

__device__ __forceinline__ void mma16816(float* c, const uint32_t* a, uint32_t b0, uint32_t b1) {
    asm volatile("mma.sync.aligned.m16n8k16.row.col.f32.f16.f16.f32 "
                 "{%0,%1,%2,%3}, {%4,%5,%6,%7}, {%8,%9}, {%0,%1,%2,%3};"
                 : "+f"(c[0]), "+f"(c[1]), "+f"(c[2]), "+f"(c[3])
                 : "r"(a[0]), "r"(a[1]), "r"(a[2]), "r"(a[3]), "r"(b0), "r"(b1));
}

// ---------------- conversion helpers ----------------
__device__ __forceinline__ uint4 pack8(float4 a, float4 b) {
    __half2 h0 = __floats2half2_rn(a.x, a.y);
    __half2 h1 = __floats2half2_rn(a.z, a.w);
    __half2 h2 = __floats2half2_rn(b.x, b.y);
    __half2 h3 = __floats2half2_rn(b.z, b.w);
    uint4 u;
    u.x = *reinterpret_cast<uint32_t*>(&h0);
    u.y = *reinterpret_cast<uint32_t*>(&h1);
    u.z = *reinterpret_cast<uint32_t*>(&h2);
    u.w = *reinterpret_cast<uint32_t*>(&h3);
    return u;
}

// prep1: lora_A -> ah (fp16, PERMUTED rows) + reset all cross-kernel counters.
// x and W conversion happen inside the fused launch (worker blocks, K-slab order).
__global__ void __launch_bounds__(256)
prep1_kernel(const float* __restrict__ lA, __half* __restrict__ ah) {
    if (blockIdx.x == 0) {
        if (threadIdx.x < 66) g_slabcnt[threadIdx.x] = 0;
        else if (threadIdx.x == 66) g_done = 0;
        else if (threadIdx.x == 67) g_wready = 0;
    }
    int idx = blockIdx.x * blockDim.x + threadIdx.x;
    if (idx < 3 * SEXT * 512) {
        // lora_A natural row = s*48 + i*16 + r; permute to drow = i*128 + s*16 + r
        // so GEMM1 output columns land directly in per-target (i, s, r) layout.
        int row = idx >> 9, c8 = idx & 511;
        int s = row / 48, rem = row % 48;
        int i = rem >> 4, r = rem & 15;
        int drow = i * SEXT + s * RANK + r;
        const float4* p = reinterpret_cast<const float4*>(lA + (size_t)row * HID + (size_t)c8 * 8);
        float4 f0 = p[0], f1 = p[1];
        *reinterpret_cast<uint4*>(ah + (size_t)drow * HID + (size_t)c8 * 8) = pack8(f0, f1);
    }
}

// ---------------- conversion worker (runs inside the fused launch) ----------------
// NW blocks sweep K-slabs c = 0..65 IN ORDER. Slab c (c<64): x cols [64c,64c+64)
// (65536 16B-granules) + W cols (49152 granules). Slabs 64,65: W-ext columns from
// bq/bk/bv. After each slab: __syncthreads -> tid0: threadfence (release) +
// atomicAdd(slabcnt); the NW-th arrival publishes g_wready = c+1 (monotone by
// construction since every block finishes slab c before slab c+1).
// 9 independent unrolled 32B loads/thread/slab across 13312 threads ≈ 3.4 MB in
// flight -> DRAM-saturating (R12/R13's serial-chain workers were latency-bound).
__device__ __forceinline__ void worker_body(
    int b, const float* __restrict__ x, const float* __restrict__ W,
    const float* __restrict__ bq, const float* __restrict__ bk,
    const float* __restrict__ bv,
    __half* __restrict__ xh, __half* __restrict__ wh) {
    const int tid = threadIdx.x;
    const int lane_g = b * 128 + tid;         // 0..13311
    constexpr int STRIDE = NW * 128;          // 13312
    constexpr int XG = T_TOK * 8;             // 65536 x-granules per slab
    constexpr int WG = NOUT * 8;              // 49152 W-granules per slab

    for (int c = 0; c < 64; c++) {
        #pragma unroll
        for (int q = 0; q < 9; q++) {
            int gidx = q * STRIDE + lane_g;
            if (gidx < XG + WG) {
                if (gidx < XG) {
                    int row = gidx >> 3, k = gidx & 7;
                    const float4* p = reinterpret_cast<const float4*>(
                        x + (size_t)row * HID + c * 64 + 8 * k);
                    float4 f0 = p[0], f1 = p[1];
                    *reinterpret_cast<uint4*>(xh + (size_t)row * HID + c * 64 + 8 * k)
                        = pack8(f0, f1);
                } else {
                    int g2 = gidx - XG;
                    int row = g2 >> 3, k = g2 & 7;
                    const float4* p = reinterpret_cast<const float4*>(
                        W + (size_t)row * HID + c * 64 + 8 * k);
                    float4 f0 = p[0], f1 = p[1];
                    *reinterpret_cast<uint4*>(wh + (size_t)row * KTOT2 + c * 64 + 8 * k)
                        = pack8(f0, f1);
                }
            }
        }
        __syncthreads();
        if (tid == 0) {
            __threadfence();
            unsigned old = atomicAdd(&g_slabcnt[c], 1u);
            if (old == NW - 1) atomicMax(&g_wready, (unsigned)(c + 1));
        }
    }
    // ext slabs 64, 65: wh[n, 4096+j] = B_sec(n)[s, n_local, r], j = s*16 + r
    for (int c = 64; c < 66; c++) {
        int j0 = (c - 64) * 64;
        #pragma unroll
        for (int q = 0; q < 15; q++) {
            int e2 = q * STRIDE + lane_g;      // half2 index: 6144 rows x 32 pairs
            if (e2 < NOUT * 32) {
                int n = e2 >> 5, jj2 = e2 & 31;
                int j = j0 + jj2 * 2;          // even -> r,r+1 in same slot s
                int s = j >> 4, r = j & 15;
                const float* bsrc;
                if (n < QS)            bsrc = bq + ((size_t)s * QS + n) * RANK;
                else if (n < QS + KVS) bsrc = bk + ((size_t)s * KVS + (n - QS)) * RANK;
                else                   bsrc = bv + ((size_t)s * KVS + (n - QS - KVS)) * RANK;
                __half2 h = __floats2half2_rn(bsrc[r], bsrc[r + 1]);
                *reinterpret_cast<__half2*>(wh + (size_t)n * KTOT2 + HID + j) = h;
            }
        }
        __syncthreads();
        if (tid == 0) {
            __threadfence();
            unsigned old = atomicAdd(&g_slabcnt[c], 1u);
            if (old == NW - 1) atomicMax(&g_wready, (unsigned)(c + 1));
        }
    }
}

// ---------------- GEMM body (R14 inner loop + K-slab gating) ----------------
// 128x128 CTA tile, 128 threads (4 warps 2x2, warp tile 64x64), 3-stage cp.async
// (96 KB) -> 2 CTAs/SM, decoupled barriers. RACE-FREE cross-chunk fragment
// pipelining: next chunk's ks0 fragments load only AFTER CP_WAIT(1)+__syncthreads
// (pre-barrier loads are a data race; see R9). Single fragment buffers (R15's
// double-buffer hit the 255-reg wall and regressed).
// NEW: load_stage(c) first waits g_wready > c (workers produce xh/wh K-slabs in
// order; acquire = volatile poll + threadfence). Wave 1 = NW workers + all NT1
// G1 tiles (exactly 296 slots) -> every producer is resident: deadlock-free.
// G1: B=ah (ld HID), nct=64, LoRA route/scale epilogue -> ext bufs, then
//     threadfence + atomicAdd(g_done).
// G2: B=wh (ld 4224), nct=66; chunks >= 64 read xe -> spin g_done==NT1 (G2 CTAs
//     start after wave 1, so this never actually spins).
template<bool G1>
__device__ __forceinline__ void gemm_body(
    int tv, const __half* __restrict__ A, const __half* __restrict__ Bp,
    float* __restrict__ C, const int* __restrict__ t2s, const float* __restrict__ sc,
    __half* __restrict__ e0, __half* __restrict__ e1, __half* __restrict__ e2,
    char* smem) {
    constexpr int BM = 128, BN = 128, BK = 64;
    constexpr int THREADS = 128;
    constexpr int STAGE_A = BM * BK * 2;          // 16 KB
    constexpr int STAGE_B = BN * BK * 2;          // 16 KB
    constexpr int STAGE   = STAGE_A + STAGE_B;    // 32 KB
    constexpr int NSTAGE  = 3;
    constexpr int MT  = 4;                        // 16-row m-tiles per warp (64 rows)
    constexpr int NTL = 8;                        // 8-col n-tiles per warp (64 cols)
    constexpr int NPAIR = 4;                      // ldmatrix.x4 loads for B per k-step
    constexpr int ntn    = G1 ? 3 : 48;
    constexpr int ldb    = G1 ? HID : KTOT2;
    constexpr int nctot  = G1 ? 64 : 66;
    constexpr int NCBASE = 64;                    // chunks < 64 come from A (xh)

    const int tid  = threadIdx.x;
    const int wid  = tid >> 5, lane = tid & 31;
    const int wm   = wid & 1, wn = wid >> 1;      // 2 x 2 warp grid
    const int m0   = (tv / ntn) * BM;
    const int n0   = (tv % ntn) * BN;
    const uint32_t s_base = smem_u32(smem);

    const __half* AE = nullptr;                   // G2 ext tail source
    if constexpr (!G1) AE = (n0 < QS) ? e0 : (n0 < QS + KVS) ? e1 : e2;

    const int lr   = lane & 7;   // row within 8x8 ldmatrix
    const int lsub = lane >> 3;  // which 8x8 matrix this lane's address feeds
    const int g    = lane >> 2;  // mma group row
    const int t    = lane & 3;   // mma thread-in-group

    bool flag_seen = G1;         // G1 tiles never wait on g_done
    unsigned wlvl = 0;           // cached g_wready level

    auto wait_slab = [&](int c) {
        if (wlvl <= (unsigned)c) {
            unsigned v = *((volatile unsigned*)&g_wready);
            while (v <= (unsigned)c) {
                asm volatile("nanosleep.u32 64;");
                v = *((volatile unsigned*)&g_wready);
            }
            wlvl = v;
            __threadfence();     // acquire: order subsequent xh/wh reads
        }
    };

    auto load_stage = [&](int stage, int c) {
        wait_slab(c);            // xh slab c (A side) and wh slab c (B side) ready
        const uint32_t sa = s_base + stage * STAGE;
        const __half* srcA; size_t ldA;
        if constexpr (G1) {
            srcA = A + (size_t)m0 * HID + (size_t)c * BK; ldA = (size_t)HID;
        } else {
            if (c < NCBASE) {
                srcA = A + (size_t)m0 * HID + (size_t)c * BK; ldA = (size_t)HID;
            } else {
                if (!flag_seen) {
                    while (*((volatile unsigned*)&g_done) < (unsigned)NT1) {
                        asm volatile("nanosleep.u32 64;");
                    }
                    __threadfence();
                    flag_seen = true;
                }
                srcA = AE + (size_t)m0 * SEXT + (size_t)(c - NCBASE) * BK; ldA = SEXT;
            }
        }
        const __half* srcB = Bp + (size_t)n0 * ldb + (size_t)c * BK;
        #pragma unroll
        for (int i = 0; i < BM * 8 / THREADS; i++) {
            int id = tid + i * THREADS; int row = id >> 3, cc = id & 7;
            uint32_t off = (uint32_t)(row * 128 + cc * 16);
            cp_async16(sa + sw128(off), (const char*)srcA + row * ldA * 2 + cc * 16);
        }
        #pragma unroll
        for (int i = 0; i < BN * 8 / THREADS; i++) {
            int id = tid + i * THREADS; int row = id >> 3, cc = id & 7;
            uint32_t off = (uint32_t)(row * 128 + cc * 16);
            cp_async16(sa + STAGE_A + sw128(off), (const char*)srcB + (size_t)row * ldb * 2 + cc * 16);
        }
        CP_COMMIT();
    };

    #pragma unroll
    for (int s = 0; s < NSTAGE; s++) load_stage(s, s);   // prologue: 3 stages in flight

    float acc[MT][NTL][4];
    #pragma unroll
    for (int mi = 0; mi < MT; mi++)
        #pragma unroll
        for (int ni = 0; ni < NTL; ni++)
            #pragma unroll
            for (int q = 0; q < 4; q++) acc[mi][ni][q] = 0.f;

    uint32_t afr[MT][4], bfr[NPAIR][4];

    // fragment loads for k-step ks of the stage at smem offsets (sa, sb)
    auto frag_load = [&](uint32_t sa, uint32_t sb, int ks) {
        #pragma unroll
        for (int mi = 0; mi < MT; mi++) {
            int row  = wm * 64 + mi * 16 + (lsub & 1) * 8 + lr;
            int colh = ks * 16 + (lsub >> 1) * 8;
            uint32_t off = (uint32_t)(row * 128 + colh * 2);
            ldmatrix_x4(afr[mi], sa + sw128(off));
        }
        #pragma unroll
        for (int pi = 0; pi < NPAIR; pi++) {
            int row  = wn * 64 + pi * 16 + (lsub >> 1) * 8 + lr;
            int colh = ks * 16 + (lsub & 1) * 8;
            uint32_t off = (uint32_t)(row * 128 + colh * 2);
            ldmatrix_x4(bfr[pi], sb + sw128(off));
        }
    };

    // wait for chunk 0 (3 groups outstanding -> <=2 leaves chunk 0 complete)
    CP_WAIT(2);
    __syncthreads();
    frag_load(s_base, s_base + STAGE_A, 0);

    int stage_c = 0;
    for (int c = 0; c < nctot; c++) {
        const uint32_t sa = s_base + stage_c * STAGE;
        const uint32_t sb = sa + STAGE_A;
        const int stage_n = (stage_c + 1 == NSTAGE) ? 0 : stage_c + 1;
        const uint32_t sa_n = s_base + stage_n * STAGE;

        #pragma unroll
        for (int ks = 0; ks < 4; ks++) {
            // MMAs consume the fragments loaded for this ks (ks0 was preloaded
            // after the previous iteration's barrier)
            #pragma unroll
            for (int mi = 0; mi < MT; mi++)
                #pragma unroll
                for (int ni = 0; ni < NTL; ni++)
                    mma16816(acc[mi][ni], afr[mi],
                             bfr[ni >> 1][(ni & 1) * 2 + 0],
                             bfr[ni >> 1][(ni & 1) * 2 + 1]);
            if (ks < 3) frag_load(sa, sb, ks + 1);
        }

        // complete chunk c+1 in THIS thread, then barrier: all threads' waits
        // have executed -> chunk c+1 smem writes published, stage (c%3) reads done.
        CP_WAIT(1);
        __syncthreads();
        if (c + 1 < nctot) frag_load(sa_n, sa_n + STAGE_A, 0);  // safe: post-barrier
        if (c + NSTAGE < nctot) load_stage(stage_c, c + NSTAGE);
        else CP_COMMIT();  // keep group count uniform
        stage_c = stage_n;
    }

    if constexpr (G1) {
        // LoRA down-proj epilogue: route + scale + fp16 store into per-target ext
        // bufs. Column j in [0,384) is per-target order (prep permuted lora_A):
        // target = j>>7, rem = j&127 = slot*16 + rank.
        #pragma unroll
        for (int mi = 0; mi < MT; mi++) {
            int r0 = m0 + wm * 64 + mi * 16 + g;
            int slot0 = t2s[r0], slot1 = t2s[r0 + 8];
            float s0 = sc[slot0], s1 = sc[slot1];
            #pragma unroll
            for (int ni = 0; ni < NTL; ni++) {
                int j = n0 + wn * 64 + ni * 8 + 2 * t;
                int it = j >> 7, rem = j & 127;
                int s = rem >> 4;
                __half* ebuf = (it == 0) ? e0 : (it == 1) ? e1 : e2;
                __half2 h0 = (s == slot0)
                    ? __floats2half2_rn(s0 * acc[mi][ni][0], s0 * acc[mi][ni][1])
                    : __floats2half2_rn(0.f, 0.f);
                __half2 h1 = (s == slot1)
                    ? __floats2half2_rn(s1 * acc[mi][ni][2], s1 * acc[mi][ni][3])
                    : __floats2half2_rn(0.f, 0.f);
                *reinterpret_cast<__half2*>(ebuf + (size_t)r0 * SEXT + rem)       = h0;
                *reinterpret_cast<__half2*>(ebuf + (size_t)(r0 + 8) * SEXT + rem) = h1;
            }
        }
        // release: xe visible, then count this tile done
        __threadfence();
        __syncthreads();
        if (tid == 0) atomicAdd(&g_done, 1u);
    } else {
        // fp32 epilogue: streaming stores (write-once output; don't evict the
        // L2-resident W stream that every wave re-reads)
        #pragma unroll
        for (int mi = 0; mi < MT; mi++) {
            int r0 = m0 + wm * 64 + mi * 16 + g;
            #pragma unroll
            for (int ni = 0; ni < NTL; ni++) {
                int col = n0 + wn * 64 + ni * 8 + 2 * t;
                float2 v0 = make_float2(acc[mi][ni][0], acc[mi][ni][1]);
                float2 v1 = make_float2(acc[mi][ni][2], acc[mi][ni][3]);
                __stcs(reinterpret_cast<float2*>(C + (size_t)r0 * NOUT + col), v0);
                __stcs(reinterpret_cast<float2*>(C + (size_t)(r0 + 8) * NOUT + col), v1);
            }
        }
    }
}

// ---------------- fused workers + GEMM1 + GEMM2 (single launch) ----------------
// Block order: [0,NW) conversion workers, [NW, NW+NT1) G1 tiles, rest G2 tiles.
// Wave 1 = NW + NT1 = 296 blocks = all producers resident from t=0.
__global__ void __launch_bounds__(128, 2)
hgemm_fused_kernel(const __half* __restrict__ A, const __half* __restrict__ B1,
                   const __half* __restrict__ B2, float* __restrict__ C,
                   const int* __restrict__ t2s, const float* __restrict__ sc,
                   __half* __restrict__ e0, __half* __restrict__ e1,
                   __half* __restrict__ e2,
                   const float* __restrict__ x, const float* __restrict__ W,
                   const float* __restrict__ bq, const float* __restrict__ bk,
                   const float* __restrict__ bv,
                   __half* __restrict__ xhd, __half* __restrict__ whd) {
    extern __shared__ char smem[];
    const int tau = (int)blockIdx.x;
    if (tau < NW) {
        worker_body(tau, x, W, bq, bk, bv, xhd, whd);
    } else if (tau < NW + NT1) {
        gemm_body<true >(tau - NW,       A, B1, C, t2s, sc, e0, e1, e2, smem);
    } else {
        gemm_body<false>(tau - NW - NT1, A, B2, C, t2s, sc, e0, e1, e2, smem);
    }
}

// ---------------- launch ----------------
extern "C" void kernel_launch(void* const* d_in, const int* in_sizes, int n_in,
                              void* d_out, int out_size) {
    (void)in_sizes; (void)n_in; (void)out_size;
    const float* x   = (const float*)d_in[0];
    const float* W   = (const float*)d_in[1];
    const float* lA  = (const float*)d_in[2];
    const float* bq  = (const float*)d_in[3];
    const float* bk  = (const float*)d_in[4];
    const float* bv  = (const float*)d_in[5];
    const float* sc  = (const float*)d_in[6];
    const int*   t2s = (const int*)d_in[7];
    float* out = (float*)d_out;

    void *xh_p, *wh_p, *ah_p, *xe_p;
    cudaGetSymbolAddress(&xh_p, g_xh);
    cudaGetSymbolAddress(&wh_p, g_wh);
    cudaGetSymbolAddress(&ah_p, g_ah);
    cudaGetSymbolAddress(&xe_p, g_xe);
    __half* xh = (__half*)xh_p;
    __half* wh = (__half*)wh_p;
    __half* ah = (__half*)ah_p;
    __half* xe0 = (__half*)xe_p;
    __half* xe1 = xe0 + (size_t)T_TOK * SEXT;
    __half* xe2 = xe1 + (size_t)T_TOK * SEXT;

    constexpr int SMEM = 3 * (128 * 64 * 2 + 128 * 64 * 2);  // 98304 (2 CTAs/SM)
    cudaFuncSetAttribute((const void*)hgemm_fused_kernel,
                         cudaFuncAttributeMaxDynamicSharedMemorySize, SMEM);

    // 1) prep1: lora_A permute (3 MB) + reset g_done / g_wready / g_slabcnt.
    prep1_kernel<<<(3 * SEXT * 512 + 255) / 256, 256>>>(lA, ah);

    // 2) fused: NW conversion workers (x->xh, W->wh by K-slab, publishing g_wready)
    //    + 192 G1 tiles + 3072 G2 tiles, all gated on slab readiness.
    {
        int grid = NW + NT1 + (NOUT / 128) * (T_TOK / 128);  // 104+192+3072 = 3368
        hgemm_fused_kernel<<<grid, 128, SMEM>>>(
            xh, ah, wh, out, t2s, sc, xe0, xe1, xe2,
            x, W, bq, bk, bv, xh, wh);
    }
}